// round 15
// baseline (speedup 1.0000x reference)
#include <cuda_runtime.h>
#include <cstdint>

#define NE 256
#define NC 48
#define NB 64
#define NT 1024
#define MROWS 64          // GEMM M-tile (4 warps x 16)
#define KT   64           // K-tile (floats)
#define PADK 68           // padded row stride: %32==4 -> conflict-free
#define BFLO (NC * PADK)            // 3264 floats: B tile
#define AFLO (MROWS * PADK)         // 4352 floats: A tile
#define TILE_FLOATS (BFLO + AFLO)   // 7616
#define GEMM_SMEM (2 * TILE_FLOATS * 4 + MROWS * 4)   // 61184 B
#define NBLK (NB * NT / MROWS)      // 1024 blocks

static __device__ float g_exp[NB * NT * NC];   // exp(logits) (12.6 MB)
static __device__ float g_partial[NB];
static __device__ int   g_done;     // zero-init; self-resets each run

// ---------- helpers ----------
__device__ __forceinline__ unsigned long long ffma2(unsigned long long a, unsigned long long b,
                                                    unsigned long long c) {
    unsigned long long d;
    asm("fma.rn.f32x2 %0, %1, %2, %3;" : "=l"(d) : "l"(a), "l"(b), "l"(c));
    return d;
}
__device__ __forceinline__ unsigned long long fadd2(unsigned long long a, unsigned long long b) {
    unsigned long long d;
    asm("add.rn.f32x2 %0, %1, %2;" : "=l"(d) : "l"(a), "l"(b));
    return d;
}
__device__ __forceinline__ float2 unpack2(unsigned long long a) {
    float2 f;
    asm("mov.b64 {%0, %1}, %2;" : "=f"(f.x), "=f"(f.y) : "l"(a));
    return f;
}
__device__ __forceinline__ unsigned long long pack2(float x, float y) {
    unsigned long long d;
    asm("mov.b64 %0, {%1, %2};" : "=l"(d) : "f"(x), "f"(y));
    return d;
}
__device__ __forceinline__ float frcp_fast(float x) {
    float r; asm("rcp.approx.f32 %0, %1;" : "=f"(r) : "f"(x)); return r;
}
__device__ __forceinline__ uint32_t smem_u32(const void* p) {
    uint32_t a;
    asm("{ .reg .u64 t; cvta.to.shared.u64 t, %1; cvt.u32.u64 %0, t; }" : "=r"(a) : "l"(p));
    return a;
}
__device__ __forceinline__ void ldgsts16(uint32_t dst, const void* src) {
    asm volatile("cp.async.cg.shared.global [%0], [%1], 16;" :: "r"(dst), "l"(src));
}
__device__ __forceinline__ uint32_t f2tf32(float x) {
    uint32_t r; asm("cvt.rna.tf32.f32 %0, %1;" : "=r"(r) : "f"(x)); return r;
}
__device__ __forceinline__ void mma_tf32(float& d0, float& d1, float& d2, float& d3,
                                         uint32_t a0, uint32_t a1, uint32_t a2, uint32_t a3,
                                         uint32_t b0, uint32_t b1) {
    asm volatile(
        "mma.sync.aligned.m16n8k8.row.col.f32.tf32.tf32.f32 "
        "{%0,%1,%2,%3}, {%4,%5,%6,%7}, {%8,%9}, {%0,%1,%2,%3};"
        : "+f"(d0), "+f"(d1), "+f"(d2), "+f"(d3)
        : "r"(a0), "r"(a1), "r"(a2), "r"(a3), "r"(b0), "r"(b1));
}

// ============================================================================
// Kernel 1: tf32 tensor GEMM (R14-proven) + exp(logits) epilogue write.
// ============================================================================
__global__ __launch_bounds__(128, 3) void gemm_kernel(
    const int* __restrict__ x, const float* __restrict__ emb,
    const float* __restrict__ fcw, const float* __restrict__ fcb,
    float* __restrict__ out)
{
    extern __shared__ float sm[];
    int* x_s = (int*)(sm + 2 * TILE_FLOATS);

    const int tid  = threadIdx.x;
    const int w    = tid >> 5;
    const int lane = tid & 31;
    const int qr   = lane >> 2;       // 0..7
    const int qc   = lane & 3;        // 0..3
    const int rowBase = blockIdx.x * MROWS;

    if (tid < MROWS) x_s[tid] = x[rowBase + tid];
    __syncthreads();

    const uint32_t smbase = smem_u32(sm);

    #define LOAD_TILE(KIDX, BUF)                                               \
    {                                                                          \
        const int k0 = (KIDX) * KT;                                            \
        const uint32_t bb = smbase + (BUF) * TILE_FLOATS * 4;                  \
        const uint32_t ab = bb + BFLO * 4;                                     \
        for (int i = tid; i < 768; i += 128) {       /* B: 48 x 16 float4 */   \
            int n = i >> 4, k4 = i & 15;                                       \
            ldgsts16(bb + (n * PADK + 4 * k4) * 4,                             \
                     fcw + n * NE + k0 + 4 * k4);                              \
        }                                                                      \
        for (int i = tid; i < 1024; i += 128) {      /* A: 64 x 16 float4 */   \
            int r = i >> 4, k4 = i & 15;                                       \
            ldgsts16(ab + (r * PADK + 4 * k4) * 4,                             \
                     emb + (size_t)x_s[r] * NE + k0 + 4 * k4);                 \
        }                                                                      \
        asm volatile("cp.async.commit_group;");                                \
    }

    LOAD_TILE(0, 0);

    float acc[6][4];
    #pragma unroll
    for (int nt = 0; nt < 6; nt++)
        #pragma unroll
        for (int i = 0; i < 4; i++) acc[nt][i] = 0.f;

    for (int kt = 0; kt < 4; kt++) {
        if (kt < 3) {
            LOAD_TILE(kt + 1, (kt + 1) & 1);
            asm volatile("cp.async.wait_group %0;" :: "n"(1));
        } else {
            asm volatile("cp.async.wait_group %0;" :: "n"(0));
        }
        __syncthreads();

        const float* Bs = sm + (kt & 1) * TILE_FLOATS;
        const float* As = Bs + BFLO;
        const int rowA = 16 * w + qr;

        #pragma unroll
        for (int k8 = 0; k8 < 8; k8++) {
            const int kb = k8 * 8 + qc;
            uint32_t a0 = f2tf32(As[rowA * PADK + kb]);
            uint32_t a1 = f2tf32(As[(rowA + 8) * PADK + kb]);
            uint32_t a2 = f2tf32(As[rowA * PADK + kb + 4]);
            uint32_t a3 = f2tf32(As[(rowA + 8) * PADK + kb + 4]);
            #pragma unroll
            for (int nt = 0; nt < 6; nt++) {
                uint32_t b0 = f2tf32(Bs[(nt * 8 + qr) * PADK + kb]);
                uint32_t b1 = f2tf32(Bs[(nt * 8 + qr) * PADK + kb + 4]);
                mma_tf32(acc[nt][0], acc[nt][1], acc[nt][2], acc[nt][3],
                         a0, a1, a2, a3, b0, b1);
            }
        }
        __syncthreads();
    }
    #undef LOAD_TILE

    const int gr = rowBase + 16 * w + qr;
    #pragma unroll
    for (int nt = 0; nt < 6; nt++) {
        const int c = nt * 8 + 2 * qc;
        float v0 = acc[nt][0] + __ldg(&fcb[c]);
        float v1 = acc[nt][1] + __ldg(&fcb[c + 1]);
        float v2 = acc[nt][2] + __ldg(&fcb[c]);
        float v3 = acc[nt][3] + __ldg(&fcb[c + 1]);
        out[(size_t)gr * NC + c]           = v0;
        out[(size_t)gr * NC + c + 1]       = v1;
        out[(size_t)(gr + 8) * NC + c]     = v2;
        out[(size_t)(gr + 8) * NC + c + 1] = v3;
        g_exp[(size_t)gr * NC + c]           = __expf(v0);
        g_exp[(size_t)gr * NC + c + 1]       = __expf(v1);
        g_exp[(size_t)(gr + 8) * NC + c]     = __expf(v2);
        g_exp[(size_t)(gr + 8) * NC + c + 1] = __expf(v3);
    }
}

// ============================================================================
// Kernel 2: CRF forward scan — R7 flat loop, LEANED:
//  - emissions pre-exponentiated (g_exp): no MUFU/FMUL in the step
//  - renorm machinery only in the offset-3 step (only one where T%128==0)
// ============================================================================
__global__ __launch_bounds__(64) void crf_kernel(
    const float* __restrict__ logits,
    const int* __restrict__ labels,
    const float* __restrict__ start_trans,
    const float* __restrict__ end_trans,
    const float* __restrict__ trans,
    float* __restrict__ out, int out_size)
{
    __shared__ __align__(16) float a_sh[2][64];
    __shared__ float red[64];

    const int b   = blockIdx.x;
    const int tid = threadIdx.x;
    const float* lg  = logits + (size_t)b * NT * NC;
    const float* ge  = g_exp  + (size_t)b * NT * NC;
    const int*   lab = labels + b * NT;

    // ---- numerator (parallel over t, fixed-order reduce) ----
    float acc = 0.f;
    for (int t = tid; t < NT; t += 64) {
        int lt = lab[t];
        acc += lg[t * NC + lt];
        if (t + 1 < NT) acc += trans[lt * NC + lab[t + 1]];
    }
    if (tid == 0)  acc += start_trans[lab[0]];
    if (tid == 63) acc += end_trans[lab[NT - 1]];
    red[tid] = acc;
    __syncthreads();
    float num = 0.f;
    if (tid == 0) {
        #pragma unroll
        for (int i = 0; i < 64; i++) num += red[i];
    }

    // ---- branch-free setup ----
    const int cc = (tid < NC) ? tid : (NC - 1);

    unsigned long long Ec2[24];
    #pragma unroll
    for (int j = 0; j < 24; j++) {
        float e0 = __expf(trans[(2 * j)     * NC + cc]) * 0.015625f;  // /64
        float e1 = __expf(trans[(2 * j + 1) * NC + cc]) * 0.015625f;
        Ec2[j] = pack2(e0, e1);
    }
    float a_cur = __expf(start_trans[cc]) * ge[cc];   // exp(start + logit0)
    a_sh[0][tid] = a_cur;

    float logscale = 0.f;

    float eb[4];
    #pragma unroll
    for (int jj = 0; jj < 4; jj++) eb[jj] = ge[(1 + jj) * NC + cc];
    __syncthreads();

    int p = 0;

    // shared dot-product core
    #define CRF_DOT(SVAR)                                                      \
        unsigned long long s0 = 0ull, s1 = 0ull, s2 = 0ull, s3 = 0ull;         \
        _Pragma("unroll")                                                      \
        for (int j = 0; j < 12; j += 2) {                                      \
            ulonglong2 u = *(const ulonglong2*)&a_sh[p][4 * j];                \
            ulonglong2 v = *(const ulonglong2*)&a_sh[p][4 * j + 4];            \
            s0 = ffma2(u.x, Ec2[2 * j],     s0);                               \
            s1 = ffma2(u.y, Ec2[2 * j + 1], s1);                               \
            s2 = ffma2(v.x, Ec2[2 * j + 2], s2);                               \
            s3 = ffma2(v.y, Ec2[2 * j + 3], s3);                               \
        }                                                                      \
        float2 sp = unpack2(fadd2(fadd2(s0, s2), fadd2(s1, s3)));              \
        float SVAR = sp.x + sp.y;

    // lean step: no renorm machinery
    #define CRF_STEP_N(EX)                                                     \
    {                                                                          \
        CRF_DOT(s)                                                             \
        float anew = s * (EX);                                                 \
        a_sh[p ^ 1][tid] = anew;                                               \
        a_cur = anew;                                                          \
        __syncthreads();                                                       \
        p ^= 1;                                                                \
    }

    // renorm-capable step (only offset-3 steps can have T%128==0)
    #define CRF_STEP_R(T, EX)                                                  \
    {                                                                          \
        float r = a_sh[p][0];                                                  \
        CRF_DOT(s)                                                             \
        bool rn = ((T) & 127) == 0;                                            \
        float sel = rn ? frcp_fast(r) : 1.0f;                                  \
        logscale += rn ? __logf(r) : 0.0f;                                     \
        float anew = s * (EX) * sel;                                           \
        a_sh[p ^ 1][tid] = anew;                                               \
        a_cur = anew;                                                          \
        __syncthreads();                                                       \
        p ^= 1;                                                                \
    }

    // main loop: t = 1 .. 1020 (tb = 1,5,...,1017); renorm only at t%128==0,
    // which is always the tb+3 slot (t = 4k). Renorms fire at 128..896.
    for (int tb = 1; tb + 3 < NT; tb += 4) {
        float en[4];
        #pragma unroll
        for (int jj = 0; jj < 4; jj++) {
            int tt = tb + 4 + jj;
            tt = (tt < NT) ? tt : (NT - 1);
            en[jj] = ge[tt * NC + cc];
        }
        CRF_STEP_N(eb[0]);
        CRF_STEP_N(eb[1]);
        CRF_STEP_N(eb[2]);
        CRF_STEP_R(tb + 3, eb[3]);
        eb[0] = en[0]; eb[1] = en[1]; eb[2] = en[2]; eb[3] = en[3];
    }
    // epilogue: t = 1021, 1022, 1023 (no multiples of 128)
    CRF_STEP_N(eb[0]);
    CRF_STEP_N(eb[1]);
    CRF_STEP_N(eb[2]);
    #undef CRF_STEP_N
    #undef CRF_STEP_R
    #undef CRF_DOT

    // ---- logZ + per-chain partial; last block reduces everything ----
    if (tid < NC) red[tid] = a_cur * __expf(end_trans[tid]);
    __syncthreads();
    if (tid == 0) {
        float s = 0.f;
        #pragma unroll
        for (int i = 0; i < NC; i++) s += red[i];
        float logz = __logf(s) + logscale + 4254.5374f;   // + 1023*ln(64)
        g_partial[b] = num - logz;
        __threadfence();
        int v = atomicAdd(&g_done, 1);
        if (v == NB - 1) {                 // last chain: final reduce
            float tot = 0.f;
            #pragma unroll
            for (int i = 0; i < NB; i++) tot += g_partial[i];
            out[out_size - 1] = -tot;
            atomicExch(&g_done, 0);        // reset for graph replay
        }
    }
}

extern "C" void kernel_launch(void* const* d_in, const int* in_sizes, int n_in,
                              void* d_out, int out_size)
{
    const int*   x    = (const int*)  d_in[0];
    const int*   lab  = (const int*)  d_in[1];
    const float* emb  = (const float*)d_in[2];
    const float* fcw  = (const float*)d_in[3];
    const float* fcb  = (const float*)d_in[4];
    const float* st   = (const float*)d_in[5];
    const float* et   = (const float*)d_in[6];
    const float* tr   = (const float*)d_in[7];
    float* out = (float*)d_out;

    cudaFuncSetAttribute(gemm_kernel, cudaFuncAttributeMaxDynamicSharedMemorySize, GEMM_SMEM);
    gemm_kernel<<<NBLK, 128, GEMM_SMEM>>>(x, emb, fcw, fcb, out);
    crf_kernel<<<NB, 64>>>(out, lab, st, et, tr, out, out_size);
}